// round 1
// baseline (speedup 1.0000x reference)
#include <cuda_runtime.h>

#define MAXN 50000
#define HID 256

// ---- device scratch (no allocs allowed) ----
__device__ float g_hs[(size_t)MAXN * HID];   // scaled GEMM output (scatter source)
__device__ float g_acc[(size_t)MAXN * HID];  // aggregation accumulator
__device__ float g_deg[MAXN];
__device__ float g_dinv[MAXN];
__device__ float g_sum[HID];
__device__ float g_sumsq[HID];
__device__ float g_bnsc[HID];
__device__ float g_bnsh[HID];
__device__ int   g_is64;

// ---- detect edge-index width (int64 vs int32) ----
__global__ void detect_kernel(const unsigned* __restrict__ e, int E) {
    __shared__ int any;
    if (threadIdx.x == 0) any = 0;
    __syncthreads();
    int nchk = 1024; if (nchk > E) nchk = E;
    int loc = 0;
    for (int i = threadIdx.x; i < nchk; i += blockDim.x) {
        if (e[2 * i + 1] != 0u) loc = 1;   // high word of src[i] if int64; random value if int32
    }
    if (loc) atomicOr(&any, 1);
    __syncthreads();
    if (threadIdx.x == 0) g_is64 = (any == 0);
}

__device__ __forceinline__ int load_idx(const void* e, long long i) {
    if (g_is64) return (int)((const long long*)e)[i];
    return ((const int*)e)[i];
}

// ---- init: deg=1 (self loop), zero BN stats ----
__global__ void init_kernel(int M) {
    int i = blockIdx.x * blockDim.x + threadIdx.x;
    if (i < M) g_deg[i] = 1.0f;
    if (i < HID) { g_sum[i] = 0.0f; g_sumsq[i] = 0.0f; }
}

__global__ void deg_kernel(const void* __restrict__ e, int E) {
    int i = blockIdx.x * blockDim.x + threadIdx.x;
    if (i >= E) return;
    int d = load_idx(e, (long long)E + i);
    atomicAdd(&g_deg[d], 1.0f);
}

__global__ void dinv_kernel(int M) {
    int i = blockIdx.x * blockDim.x + threadIdx.x;
    if (i < M) g_dinv[i] = rsqrtf(g_deg[i]);   // deg >= 1 always (self loop)
}

// ---- tiled SGEMM: C[M,256] = A[M,K] @ B[K,256]; epilogue scales row by dinv
//      and stores to BOTH out0 (scatter source) and out1 (accumulator init = self loop).
//      APPLY_BN folds y = a*bnsc[k] + bnsh[k] into the A-tile load.
template <int K, bool APPLY_BN>
__global__ void __launch_bounds__(256)
sgemm_scaled(const float* __restrict__ A, const float* __restrict__ B,
             float* __restrict__ out0, float* __restrict__ out1, int M) {
    const int N = HID;
    __shared__ float As[8][128];
    __shared__ float Bs[8][128];
    const int tid = threadIdx.x;
    const int rowBase = blockIdx.y * 128;
    const int colBase = blockIdx.x * 128;

    const int arow = tid >> 1;          // 0..127
    const int acol = (tid & 1) * 4;     // 0 or 4
    const int brow = tid >> 5;          // 0..7
    const int bcol = (tid & 31) * 4;    // 0..124

    const int ty = tid >> 4, tx = tid & 15;
    float acc[8][8];
#pragma unroll
    for (int i = 0; i < 8; i++)
#pragma unroll
        for (int j = 0; j < 8; j++) acc[i][j] = 0.0f;

    int aRowG = rowBase + arow;
    if (aRowG >= M) aRowG = M - 1;   // clamp; stores are predicated

    for (int k0 = 0; k0 < K; k0 += 8) {
        float4 av = *(const float4*)(A + (long long)aRowG * K + k0 + acol);
        if (APPLY_BN) {
            const float4 sc = *(const float4*)(g_bnsc + k0 + acol);
            const float4 sh = *(const float4*)(g_bnsh + k0 + acol);
            av.x = fmaf(av.x, sc.x, sh.x);
            av.y = fmaf(av.y, sc.y, sh.y);
            av.z = fmaf(av.z, sc.z, sh.z);
            av.w = fmaf(av.w, sc.w, sh.w);
        }
        As[acol + 0][arow] = av.x;
        As[acol + 1][arow] = av.y;
        As[acol + 2][arow] = av.z;
        As[acol + 3][arow] = av.w;

        float4 bv = *(const float4*)(B + (long long)(k0 + brow) * N + colBase + bcol);
        *(float4*)&Bs[brow][bcol] = bv;
        __syncthreads();

#pragma unroll
        for (int kk = 0; kk < 8; kk++) {
            float a[8], b[8];
            *(float4*)(a)     = *(const float4*)&As[kk][ty * 8];
            *(float4*)(a + 4) = *(const float4*)&As[kk][ty * 8 + 4];
            *(float4*)(b)     = *(const float4*)&Bs[kk][tx * 8];
            *(float4*)(b + 4) = *(const float4*)&Bs[kk][tx * 8 + 4];
#pragma unroll
            for (int i = 0; i < 8; i++)
#pragma unroll
                for (int j = 0; j < 8; j++)
                    acc[i][j] = fmaf(a[i], b[j], acc[i][j]);
        }
        __syncthreads();
    }

#pragma unroll
    for (int i = 0; i < 8; i++) {
        int r = rowBase + ty * 8 + i;
        if (r < M) {
            float dv = g_dinv[r];
#pragma unroll
            for (int j4 = 0; j4 < 8; j4 += 4) {
                float4 v;
                v.x = acc[i][j4 + 0] * dv;
                v.y = acc[i][j4 + 1] * dv;
                v.z = acc[i][j4 + 2] * dv;
                v.w = acc[i][j4 + 3] * dv;
                int c = colBase + tx * 8 + j4;
                *(float4*)(out0 + (long long)r * N + c) = v;
                *(float4*)(out1 + (long long)r * N + c) = v;
            }
        }
    }
}

// ---- edge scatter: acc[dst] += hs[src], 64 threads/edge, float4 gather + 4 atomics
__global__ void scatter_kernel(const void* __restrict__ e, int E,
                               const float* __restrict__ hs, float* __restrict__ acc) {
    long long gid = (long long)blockIdx.x * blockDim.x + threadIdx.x;
    long long edge = gid >> 6;
    if (edge >= E) return;
    int f = (int)(gid & 63) * 4;
    int s, d;
    if (g_is64) {
        const long long* p = (const long long*)e;
        s = (int)p[edge];
        d = (int)p[E + edge];
    } else {
        const int* p = (const int*)e;
        s = p[edge];
        d = p[E + edge];
    }
    float4 v = *(const float4*)(hs + (long long)s * HID + f);
    float* a = acc + (long long)d * HID + f;
    atomicAdd(a + 0, v.x);
    atomicAdd(a + 1, v.y);
    atomicAdd(a + 2, v.z);
    atomicAdd(a + 3, v.w);
}

// ---- layer-1 tail: h = relu(acc*dinv + b1), write to outh, accumulate BN stats
__global__ void pass1_kernel(const float* __restrict__ acc, const float* __restrict__ b1,
                             float* __restrict__ outh, int M) {
    int f = threadIdx.x;           // 256 = HID
    float bias = b1[f];
    float s = 0.0f, s2 = 0.0f;
    for (int r = blockIdx.x; r < M; r += gridDim.x) {
        float v = fmaf(acc[(long long)r * HID + f], g_dinv[r], bias);
        v = fmaxf(v, 0.0f);
        outh[(long long)r * HID + f] = v;
        s += v;
        s2 += v * v;
    }
    atomicAdd(&g_sum[f], s);
    atomicAdd(&g_sumsq[f], s2);
}

__global__ void bn_finalize(const float* __restrict__ gamma, const float* __restrict__ beta,
                            float invM) {
    int f = threadIdx.x;
    float mean = g_sum[f] * invM;
    float var = fmaf(-mean, mean, g_sumsq[f] * invM);
    float rstd = rsqrtf(var + 1e-5f);
    float sc = gamma[f] * rstd;
    g_bnsc[f] = sc;
    g_bnsh[f] = fmaf(-mean, sc, beta[f]);
}

// ---- layer-2 tail: out = out*dinv[row] + b2 (in place)
__global__ void finish_kernel(float* __restrict__ out, const float* __restrict__ b2, int M) {
    long long gid = (long long)blockIdx.x * blockDim.x + threadIdx.x;
    long long r = gid >> 6;
    if (r >= M) return;
    int f = (int)(gid & 63) * 4;
    float dv = g_dinv[r];
    float4 v = *(float4*)(out + r * HID + f);
    float4 bb = *(const float4*)(b2 + f);
    v.x = fmaf(v.x, dv, bb.x);
    v.y = fmaf(v.y, dv, bb.y);
    v.z = fmaf(v.z, dv, bb.z);
    v.w = fmaf(v.w, dv, bb.w);
    *(float4*)(out + r * HID + f) = v;
}

extern "C" void kernel_launch(void* const* d_in, const int* in_sizes, int n_in,
                              void* d_out, int out_size) {
    const float* x     = (const float*)d_in[0];
    const void*  eidx  = d_in[1];
    const float* W1    = (const float*)d_in[2];
    const float* b1    = (const float*)d_in[3];
    const float* gamma = (const float*)d_in[4];
    const float* beta  = (const float*)d_in[5];
    const float* W2    = (const float*)d_in[6];
    const float* b2    = (const float*)d_in[7];
    float* out = (float*)d_out;

    const int Kin = 128;
    const int M = in_sizes[0] / Kin;     // 50000
    const int E = in_sizes[1] / 2;       // 800000

    float *hs, *acc;
    cudaGetSymbolAddress((void**)&hs, g_hs);
    cudaGetSymbolAddress((void**)&acc, g_acc);

    detect_kernel<<<1, 256>>>((const unsigned*)eidx, E);
    init_kernel<<<(M + 255) / 256, 256>>>(M);
    deg_kernel<<<(E + 255) / 256, 256>>>(eidx, E);
    dinv_kernel<<<(M + 255) / 256, 256>>>(M);

    dim3 gemm_grid(HID / 128, (M + 127) / 128);
    // layer 1: hs = (x@W1)*dinv[row]; acc initialized to hs (self loop)
    sgemm_scaled<128, false><<<gemm_grid, 256>>>(x, W1, hs, acc, M);

    long long sthreads = (long long)E * 64;
    int sblocks = (int)((sthreads + 255) / 256);
    scatter_kernel<<<sblocks, 256>>>(eidx, E, hs, acc);

    // relu + bias + BN stats; normalized-input storage reuses hs
    pass1_kernel<<<512, 256>>>(acc, b1, hs, M);
    bn_finalize<<<1, 256>>>(gamma, beta, 1.0f / (float)M);

    // layer 2: BN applied on A-load; hs2 -> acc, accumulator init -> d_out
    sgemm_scaled<256, true><<<gemm_grid, 256>>>(hs, W2, acc, out, M);
    scatter_kernel<<<sblocks, 256>>>(eidx, E, acc, out);

    long long fthreads = (long long)M * 64;
    finish_kernel<<<(int)((fthreads + 255) / 256), 256>>>(out, b2, M);
}

// round 2
// speedup vs baseline: 1.4636x; 1.4636x over previous
#include <cuda_runtime.h>

#define MAXN 50000
#define MAXE 800000
#define HID 256

// ---- device scratch (no allocs allowed) ----
__device__ float g_hs[(size_t)MAXN * HID];   // GEMM output (gather source)
__device__ float g_acc[(size_t)MAXN * HID];  // second buffer
__device__ float g_dinv[MAXN];
__device__ int   g_cnt[MAXN];
__device__ int   g_off[MAXN + 1];
__device__ int   g_cur[MAXN];
__device__ int   g_csr[MAXE];
__device__ float g_sum[HID];
__device__ float g_sumsq[HID];
__device__ float g_bnsc[HID];
__device__ float g_bnsh[HID];
__device__ int   g_is64;

// ---- detect edge-index width (int64 vs int32) ----
__global__ void detect_kernel(const unsigned* __restrict__ e, int E) {
    __shared__ int any;
    if (threadIdx.x == 0) any = 0;
    __syncthreads();
    int nchk = 1024; if (nchk > E) nchk = E;
    int loc = 0;
    for (int i = threadIdx.x; i < nchk; i += blockDim.x) {
        if (e[2 * i + 1] != 0u) loc = 1;   // high words all 0 iff int64
    }
    if (loc) atomicOr(&any, 1);
    __syncthreads();
    if (threadIdx.x == 0) g_is64 = (any == 0);
}

// ---- init counters / BN stats ----
__global__ void init_kernel(int M) {
    int i = blockIdx.x * blockDim.x + threadIdx.x;
    if (i < M) g_cnt[i] = 0;
    if (i < HID) { g_sum[i] = 0.0f; g_sumsq[i] = 0.0f; }
}

// ---- in-degree count ----
__global__ void count_kernel(const void* __restrict__ e, int E) {
    int i = blockIdx.x * blockDim.x + threadIdx.x;
    if (i >= E) return;
    int d = g_is64 ? (int)((const long long*)e)[E + i] : ((const int*)e)[E + i];
    atomicAdd(&g_cnt[i >= 0 ? d : d], 1);
}

// ---- single-block exclusive scan of g_cnt -> g_off / g_cur; also dinv ----
__global__ void scan_kernel(int M) {
    __shared__ int sh[1024];
    __shared__ int carry;
    if (threadIdx.x == 0) carry = 0;
    __syncthreads();
    for (int base = 0; base < M; base += 1024) {
        int i = base + threadIdx.x;
        int v = (i < M) ? g_cnt[i] : 0;
        sh[threadIdx.x] = v;
        __syncthreads();
#pragma unroll
        for (int off = 1; off < 1024; off <<= 1) {
            int t = (threadIdx.x >= off) ? sh[threadIdx.x - off] : 0;
            __syncthreads();
            sh[threadIdx.x] += t;
            __syncthreads();
        }
        int excl = carry + sh[threadIdx.x] - v;
        if (i < M) {
            g_off[i] = excl;
            g_cur[i] = excl;
            g_dinv[i] = rsqrtf((float)(v + 1));   // +1 self loop
        }
        __syncthreads();
        if (threadIdx.x == 1023) carry += sh[1023];
        __syncthreads();
    }
    if (threadIdx.x == 0) g_off[M] = carry;
}

// ---- CSR fill ----
__global__ void fill_kernel(const void* __restrict__ e, int E) {
    int i = blockIdx.x * blockDim.x + threadIdx.x;
    if (i >= E) return;
    int s, d;
    if (g_is64) {
        const long long* p = (const long long*)e;
        s = (int)p[i]; d = (int)p[E + i];
    } else {
        const int* p = (const int*)e;
        s = p[i]; d = p[E + i];
    }
    int pos = atomicAdd(&g_cur[d], 1);
    g_csr[pos] = s;
}

// ---- tiled SGEMM: C[M,256] = A[M,K] @ B[K,256]; epilogue scales row by dinv.
//      APPLY_BN folds y = a*bnsc[k] + bnsh[k] into the A-tile load.
template <int K, bool APPLY_BN>
__global__ void __launch_bounds__(256)
sgemm_scaled(const float* __restrict__ A, const float* __restrict__ B,
             float* __restrict__ out0, int M) {
    const int N = HID;
    __shared__ float As[8][128];
    __shared__ float Bs[8][128];
    const int tid = threadIdx.x;
    const int rowBase = blockIdx.y * 128;
    const int colBase = blockIdx.x * 128;

    const int arow = tid >> 1;
    const int acol = (tid & 1) * 4;
    const int brow = tid >> 5;
    const int bcol = (tid & 31) * 4;

    const int ty = tid >> 4, tx = tid & 15;
    float acc[8][8];
#pragma unroll
    for (int i = 0; i < 8; i++)
#pragma unroll
        for (int j = 0; j < 8; j++) acc[i][j] = 0.0f;

    int aRowG = rowBase + arow;
    if (aRowG >= M) aRowG = M - 1;

    for (int k0 = 0; k0 < K; k0 += 8) {
        float4 av = *(const float4*)(A + (long long)aRowG * K + k0 + acol);
        if (APPLY_BN) {
            const float4 sc = *(const float4*)(g_bnsc + k0 + acol);
            const float4 sh = *(const float4*)(g_bnsh + k0 + acol);
            av.x = fmaf(av.x, sc.x, sh.x);
            av.y = fmaf(av.y, sc.y, sh.y);
            av.z = fmaf(av.z, sc.z, sh.z);
            av.w = fmaf(av.w, sc.w, sh.w);
        }
        As[acol + 0][arow] = av.x;
        As[acol + 1][arow] = av.y;
        As[acol + 2][arow] = av.z;
        As[acol + 3][arow] = av.w;

        float4 bv = *(const float4*)(B + (long long)(k0 + brow) * N + colBase + bcol);
        *(float4*)&Bs[brow][bcol] = bv;
        __syncthreads();

#pragma unroll
        for (int kk = 0; kk < 8; kk++) {
            float a[8], b[8];
            *(float4*)(a)     = *(const float4*)&As[kk][ty * 8];
            *(float4*)(a + 4) = *(const float4*)&As[kk][ty * 8 + 4];
            *(float4*)(b)     = *(const float4*)&Bs[kk][tx * 8];
            *(float4*)(b + 4) = *(const float4*)&Bs[kk][tx * 8 + 4];
#pragma unroll
            for (int i = 0; i < 8; i++)
#pragma unroll
                for (int j = 0; j < 8; j++)
                    acc[i][j] = fmaf(a[i], b[j], acc[i][j]);
        }
        __syncthreads();
    }

#pragma unroll
    for (int i = 0; i < 8; i++) {
        int r = rowBase + ty * 8 + i;
        if (r < M) {
            float dv = g_dinv[r];
#pragma unroll
            for (int j4 = 0; j4 < 8; j4 += 4) {
                float4 v;
                v.x = acc[i][j4 + 0] * dv;
                v.y = acc[i][j4 + 1] * dv;
                v.z = acc[i][j4 + 2] * dv;
                v.w = acc[i][j4 + 3] * dv;
                int c = colBase + tx * 8 + j4;
                *(float4*)(out0 + (long long)r * N + c) = v;
            }
        }
    }
}

// ---- CSR gather aggregation. One 64-thread group per dst row, float4/thread.
//      acc = src[r] (self loop) + sum_{e in row} src[csr[e]]
//      L1: out = relu(acc*dinv + bias), accumulate BN stats
//      else: out = acc*dinv + bias
template <bool L1>
__global__ void __launch_bounds__(256)
gather_kernel(const float* __restrict__ srcf, const float* __restrict__ bias,
              float* __restrict__ out, int M) {
    const int grp = threadIdx.x >> 6;
    const int f = (threadIdx.x & 63) * 4;
    const float4 bb = *(const float4*)(bias + f);
    float4 s = make_float4(0, 0, 0, 0), s2 = make_float4(0, 0, 0, 0);

    for (int r = blockIdx.x * 4 + grp; r < M; r += gridDim.x * 4) {
        int beg = g_off[r], end = g_off[r + 1];
        float4 acc = *(const float4*)(srcf + (size_t)r * HID + f);   // self loop
        int e = beg;
        for (; e + 4 <= end; e += 4) {
            int i0 = g_csr[e], i1 = g_csr[e + 1], i2 = g_csr[e + 2], i3 = g_csr[e + 3];
            float4 v0 = *(const float4*)(srcf + (size_t)i0 * HID + f);
            float4 v1 = *(const float4*)(srcf + (size_t)i1 * HID + f);
            float4 v2 = *(const float4*)(srcf + (size_t)i2 * HID + f);
            float4 v3 = *(const float4*)(srcf + (size_t)i3 * HID + f);
            v0.x += v1.x; v0.y += v1.y; v0.z += v1.z; v0.w += v1.w;
            v2.x += v3.x; v2.y += v3.y; v2.z += v3.z; v2.w += v3.w;
            acc.x += v0.x + v2.x; acc.y += v0.y + v2.y;
            acc.z += v0.z + v2.z; acc.w += v0.w + v2.w;
        }
        for (; e < end; e++) {
            int i0 = g_csr[e];
            float4 v0 = *(const float4*)(srcf + (size_t)i0 * HID + f);
            acc.x += v0.x; acc.y += v0.y; acc.z += v0.z; acc.w += v0.w;
        }
        float dv = g_dinv[r];
        float4 o;
        o.x = fmaf(acc.x, dv, bb.x);
        o.y = fmaf(acc.y, dv, bb.y);
        o.z = fmaf(acc.z, dv, bb.z);
        o.w = fmaf(acc.w, dv, bb.w);
        if (L1) {
            o.x = fmaxf(o.x, 0.0f); o.y = fmaxf(o.y, 0.0f);
            o.z = fmaxf(o.z, 0.0f); o.w = fmaxf(o.w, 0.0f);
            s.x += o.x; s.y += o.y; s.z += o.z; s.w += o.w;
            s2.x += o.x * o.x; s2.y += o.y * o.y;
            s2.z += o.z * o.z; s2.w += o.w * o.w;
        }
        *(float4*)(out + (size_t)r * HID + f) = o;
    }
    if (L1) {
        atomicAdd(&g_sum[f + 0], s.x);  atomicAdd(&g_sum[f + 1], s.y);
        atomicAdd(&g_sum[f + 2], s.z);  atomicAdd(&g_sum[f + 3], s.w);
        atomicAdd(&g_sumsq[f + 0], s2.x); atomicAdd(&g_sumsq[f + 1], s2.y);
        atomicAdd(&g_sumsq[f + 2], s2.z); atomicAdd(&g_sumsq[f + 3], s2.w);
    }
}

__global__ void bn_finalize(const float* __restrict__ gamma, const float* __restrict__ beta,
                            float invM) {
    int f = threadIdx.x;
    float mean = g_sum[f] * invM;
    float var = fmaf(-mean, mean, g_sumsq[f] * invM);
    float rstd = rsqrtf(var + 1e-5f);
    float sc = gamma[f] * rstd;
    g_bnsc[f] = sc;
    g_bnsh[f] = fmaf(-mean, sc, beta[f]);
}

extern "C" void kernel_launch(void* const* d_in, const int* in_sizes, int n_in,
                              void* d_out, int out_size) {
    const float* x     = (const float*)d_in[0];
    const void*  eidx  = d_in[1];
    const float* W1    = (const float*)d_in[2];
    const float* b1    = (const float*)d_in[3];
    const float* gamma = (const float*)d_in[4];
    const float* beta  = (const float*)d_in[5];
    const float* W2    = (const float*)d_in[6];
    const float* b2    = (const float*)d_in[7];
    float* out = (float*)d_out;

    const int Kin = 128;
    const int M = in_sizes[0] / Kin;     // 50000
    const int E = in_sizes[1] / 2;       // 800000

    float *hs, *acc;
    cudaGetSymbolAddress((void**)&hs, g_hs);
    cudaGetSymbolAddress((void**)&acc, g_acc);

    detect_kernel<<<1, 256>>>((const unsigned*)eidx, E);
    init_kernel<<<(M + 255) / 256, 256>>>(M);
    count_kernel<<<(E + 255) / 256, 256>>>(eidx, E);
    scan_kernel<<<1, 1024>>>(M);
    fill_kernel<<<(E + 255) / 256, 256>>>(eidx, E);

    dim3 gemm_grid(HID / 128, (M + 127) / 128);
    // layer 1: hs = (x@W1)*dinv[row]
    sgemm_scaled<128, false><<<gemm_grid, 256>>>(x, W1, hs, M);
    // gather + relu + bias + BN stats -> acc
    gather_kernel<true><<<2960, 256>>>(hs, b1, acc, M);
    bn_finalize<<<1, 256>>>(gamma, beta, 1.0f / (float)M);

    // layer 2: BN folded into A-load; output scaled by dinv -> hs
    sgemm_scaled<256, true><<<gemm_grid, 256>>>(acc, W2, hs, M);
    // gather + bias -> d_out
    gather_kernel<false><<<2960, 256>>>(hs, b2, out, M);
}

// round 3
// speedup vs baseline: 1.6179x; 1.1054x over previous
#include <cuda_runtime.h>

#define MAXN 50000
#define MAXE 800000
#define HID 256
#define SCAN_B 256

// ---- device scratch (no allocs allowed) ----
__device__ float g_hs[(size_t)MAXN * HID];   // GEMM output (gather source)
__device__ float g_acc[(size_t)MAXN * HID];  // second buffer
__device__ float g_dinv[MAXN];
__device__ int   g_cnt[MAXN];
__device__ int   g_off[MAXN + 1];
__device__ int   g_cur[MAXN];
__device__ int   g_csr[MAXE];
__device__ int   g_bsum[(MAXN + SCAN_B - 1) / SCAN_B + 1];
__device__ float g_sum[HID];
__device__ float g_sumsq[HID];
__device__ float g_bnsc[HID];
__device__ float g_bnsh[HID];
__device__ int   g_is64;

// ---- detect edge-index width (int64 vs int32) ----
__global__ void detect_kernel(const unsigned* __restrict__ e, int E) {
    __shared__ int any;
    if (threadIdx.x == 0) any = 0;
    __syncthreads();
    int nchk = 1024; if (nchk > E) nchk = E;
    int loc = 0;
    for (int i = threadIdx.x; i < nchk; i += blockDim.x) {
        if (e[2 * i + 1] != 0u) loc = 1;   // high words all 0 iff int64
    }
    if (loc) atomicOr(&any, 1);
    __syncthreads();
    if (threadIdx.x == 0) g_is64 = (any == 0);
}

__global__ void init_kernel(int M) {
    int i = blockIdx.x * blockDim.x + threadIdx.x;
    if (i < M) g_cnt[i] = 0;
    if (i < HID) { g_sum[i] = 0.0f; g_sumsq[i] = 0.0f; }
}

__global__ void count_kernel(const void* __restrict__ e, int E) {
    int i = blockIdx.x * blockDim.x + threadIdx.x;
    if (i >= E) return;
    int d = g_is64 ? (int)((const long long*)e)[E + i] : ((const int*)e)[E + i];
    atomicAdd(&g_cnt[d], 1);
}

// ---- scan phase A: per-block sums of g_cnt ----
__global__ void scanA_kernel(int M) {
    int i = blockIdx.x * SCAN_B + threadIdx.x;
    int v = (i < M) ? g_cnt[i] : 0;
    // warp reduce
#pragma unroll
    for (int o = 16; o > 0; o >>= 1) v += __shfl_down_sync(0xffffffffu, v, o);
    __shared__ int ws[8];
    int lane = threadIdx.x & 31, warp = threadIdx.x >> 5;
    if (lane == 0) ws[warp] = v;
    __syncthreads();
    if (warp == 0) {
        int s = (lane < 8) ? ws[lane] : 0;
#pragma unroll
        for (int o = 4; o > 0; o >>= 1) s += __shfl_down_sync(0xffffffffu, s, o);
        if (lane == 0) g_bsum[blockIdx.x] = s;
    }
}

// ---- scan phase B: exclusive scan of NB block sums (NB <= 256) ----
__global__ void scanB_kernel(int NB, int M) {
    int i = threadIdx.x;
    int v = (i < NB) ? g_bsum[i] : 0;
    int x = v;
#pragma unroll
    for (int o = 1; o < 32; o <<= 1) {
        int t = __shfl_up_sync(0xffffffffu, x, o);
        if ((threadIdx.x & 31) >= o) x += t;
    }
    __shared__ int ws[8];
    int lane = threadIdx.x & 31, warp = threadIdx.x >> 5;
    if (lane == 31) ws[warp] = x;
    __syncthreads();
    if (warp == 0 && lane < 8) {
        int s = ws[lane];
#pragma unroll
        for (int o = 1; o < 8; o <<= 1) {
            int t = __shfl_up_sync(0xffu, s, o);
            if (lane >= o) s += t;
        }
        ws[lane] = s;
    }
    __syncthreads();
    int incl = x + (warp > 0 ? ws[warp - 1] : 0);
    if (i < NB) g_bsum[i] = incl - v;       // exclusive
    if (i == NB - 1) g_off[M] = incl;       // total
}

// ---- scan phase C: block-local exclusive scan + block offset; dinv ----
__global__ void scanC_kernel(int M) {
    int i = blockIdx.x * SCAN_B + threadIdx.x;
    int v = (i < M) ? g_cnt[i] : 0;
    int x = v;
#pragma unroll
    for (int o = 1; o < 32; o <<= 1) {
        int t = __shfl_up_sync(0xffffffffu, x, o);
        if ((threadIdx.x & 31) >= o) x += t;
    }
    __shared__ int ws[8];
    int lane = threadIdx.x & 31, warp = threadIdx.x >> 5;
    if (lane == 31) ws[warp] = x;
    __syncthreads();
    if (warp == 0 && lane < 8) {
        int s = ws[lane];
#pragma unroll
        for (int o = 1; o < 8; o <<= 1) {
            int t = __shfl_up_sync(0xffu, s, o);
            if (lane >= o) s += t;
        }
        ws[lane] = s;
    }
    __syncthreads();
    if (i < M) {
        int excl = x - v + (warp > 0 ? ws[warp - 1] : 0) + g_bsum[blockIdx.x];
        g_off[i] = excl;
        g_cur[i] = excl;
        g_dinv[i] = rsqrtf((float)(v + 1));   // +1 self loop
    }
}

// ---- CSR fill ----
__global__ void fill_kernel(const void* __restrict__ e, int E) {
    int i = blockIdx.x * blockDim.x + threadIdx.x;
    if (i >= E) return;
    int s, d;
    if (g_is64) {
        const long long* p = (const long long*)e;
        s = (int)p[i]; d = (int)p[E + i];
    } else {
        const int* p = (const int*)e;
        s = p[i]; d = p[E + i];
    }
    int pos = atomicAdd(&g_cur[d], 1);
    g_csr[pos] = s;
}

// ---- double-buffered SGEMM: C[M,256] = A[M,K] @ B[K,256]; epilogue *dinv[row].
//      APPLY_BN folds y = a*bnsc[k] + bnsh[k] into the A-tile load.
template <int K, bool APPLY_BN>
__global__ void __launch_bounds__(256)
sgemm_scaled(const float* __restrict__ A, const float* __restrict__ B,
             float* __restrict__ out0, int M) {
    const int N = HID;
    __shared__ float As[2][8][128];
    __shared__ float Bs[2][8][128];
    const int tid = threadIdx.x;
    const int rowBase = blockIdx.y * 128;
    const int colBase = blockIdx.x * 128;

    const int arow = tid >> 1;
    const int acol = (tid & 1) * 4;
    const int brow = tid >> 5;
    const int bcol = (tid & 31) * 4;

    const int ty = tid >> 4, tx = tid & 15;
    float acc[8][8];
#pragma unroll
    for (int i = 0; i < 8; i++)
#pragma unroll
        for (int j = 0; j < 8; j++) acc[i][j] = 0.0f;

    int aRowG = rowBase + arow;
    if (aRowG >= M) aRowG = M - 1;
    const float* Aptr = A + (long long)aRowG * K;

    const int NT = K / 8;
    float4 av, bv;

    // preload tile 0
    av = *(const float4*)(Aptr + acol);
    if (APPLY_BN) {
        const float4 sc = *(const float4*)(g_bnsc + acol);
        const float4 sh = *(const float4*)(g_bnsh + acol);
        av.x = fmaf(av.x, sc.x, sh.x); av.y = fmaf(av.y, sc.y, sh.y);
        av.z = fmaf(av.z, sc.z, sh.z); av.w = fmaf(av.w, sc.w, sh.w);
    }
    bv = *(const float4*)(B + (long long)brow * N + colBase + bcol);
    As[0][acol + 0][arow] = av.x; As[0][acol + 1][arow] = av.y;
    As[0][acol + 2][arow] = av.z; As[0][acol + 3][arow] = av.w;
    *(float4*)&Bs[0][brow][bcol] = bv;
    __syncthreads();

    for (int kt = 0; kt < NT; kt++) {
        const int cur = kt & 1;
        const bool more = (kt + 1 < NT);
        if (more) {
            const int k0 = (kt + 1) * 8;
            av = *(const float4*)(Aptr + k0 + acol);
            if (APPLY_BN) {
                const float4 sc = *(const float4*)(g_bnsc + k0 + acol);
                const float4 sh = *(const float4*)(g_bnsh + k0 + acol);
                av.x = fmaf(av.x, sc.x, sh.x); av.y = fmaf(av.y, sc.y, sh.y);
                av.z = fmaf(av.z, sc.z, sh.z); av.w = fmaf(av.w, sc.w, sh.w);
            }
            bv = *(const float4*)(B + (long long)(k0 + brow) * N + colBase + bcol);
        }
#pragma unroll
        for (int kk = 0; kk < 8; kk++) {
            float a[8], b[8];
            *(float4*)(a)     = *(const float4*)&As[cur][kk][ty * 8];
            *(float4*)(a + 4) = *(const float4*)&As[cur][kk][ty * 8 + 4];
            *(float4*)(b)     = *(const float4*)&Bs[cur][kk][tx * 8];
            *(float4*)(b + 4) = *(const float4*)&Bs[cur][kk][tx * 8 + 4];
#pragma unroll
            for (int i = 0; i < 8; i++)
#pragma unroll
                for (int j = 0; j < 8; j++)
                    acc[i][j] = fmaf(a[i], b[j], acc[i][j]);
        }
        if (more) {
            const int nxt = cur ^ 1;
            As[nxt][acol + 0][arow] = av.x; As[nxt][acol + 1][arow] = av.y;
            As[nxt][acol + 2][arow] = av.z; As[nxt][acol + 3][arow] = av.w;
            *(float4*)&Bs[nxt][brow][bcol] = bv;
            __syncthreads();
        }
    }

#pragma unroll
    for (int i = 0; i < 8; i++) {
        int r = rowBase + ty * 8 + i;
        if (r < M) {
            float dv = g_dinv[r];
#pragma unroll
            for (int j4 = 0; j4 < 8; j4 += 4) {
                float4 v;
                v.x = acc[i][j4 + 0] * dv;
                v.y = acc[i][j4 + 1] * dv;
                v.z = acc[i][j4 + 2] * dv;
                v.w = acc[i][j4 + 3] * dv;
                int c = colBase + tx * 8 + j4;
                *(float4*)(out0 + (long long)r * N + c) = v;
            }
        }
    }
}

// ---- CSR gather aggregation: one 64-thread group per dst row, float4/thread.
template <bool L1>
__global__ void __launch_bounds__(256)
gather_kernel(const float* __restrict__ srcf, const float* __restrict__ bias,
              float* __restrict__ out, int M) {
    const int grp = threadIdx.x >> 6;
    const int f = (threadIdx.x & 63) * 4;
    const float4 bb = *(const float4*)(bias + f);
    float4 s = make_float4(0, 0, 0, 0), s2 = make_float4(0, 0, 0, 0);

    for (int r = blockIdx.x * 4 + grp; r < M; r += gridDim.x * 4) {
        int beg = g_off[r], end = g_off[r + 1];
        float4 acc = *(const float4*)(srcf + (size_t)r * HID + f);   // self loop
        int e = beg;
        for (; e + 4 <= end; e += 4) {
            int i0 = g_csr[e], i1 = g_csr[e + 1], i2 = g_csr[e + 2], i3 = g_csr[e + 3];
            float4 v0 = *(const float4*)(srcf + (size_t)i0 * HID + f);
            float4 v1 = *(const float4*)(srcf + (size_t)i1 * HID + f);
            float4 v2 = *(const float4*)(srcf + (size_t)i2 * HID + f);
            float4 v3 = *(const float4*)(srcf + (size_t)i3 * HID + f);
            v0.x += v1.x; v0.y += v1.y; v0.z += v1.z; v0.w += v1.w;
            v2.x += v3.x; v2.y += v3.y; v2.z += v3.z; v2.w += v3.w;
            acc.x += v0.x + v2.x; acc.y += v0.y + v2.y;
            acc.z += v0.z + v2.z; acc.w += v0.w + v2.w;
        }
        for (; e < end; e++) {
            int i0 = g_csr[e];
            float4 v0 = *(const float4*)(srcf + (size_t)i0 * HID + f);
            acc.x += v0.x; acc.y += v0.y; acc.z += v0.z; acc.w += v0.w;
        }
        float dv = g_dinv[r];
        float4 o;
        o.x = fmaf(acc.x, dv, bb.x);
        o.y = fmaf(acc.y, dv, bb.y);
        o.z = fmaf(acc.z, dv, bb.z);
        o.w = fmaf(acc.w, dv, bb.w);
        if (L1) {
            o.x = fmaxf(o.x, 0.0f); o.y = fmaxf(o.y, 0.0f);
            o.z = fmaxf(o.z, 0.0f); o.w = fmaxf(o.w, 0.0f);
            s.x += o.x; s.y += o.y; s.z += o.z; s.w += o.w;
            s2.x += o.x * o.x; s2.y += o.y * o.y;
            s2.z += o.z * o.z; s2.w += o.w * o.w;
        }
        *(float4*)(out + (size_t)r * HID + f) = o;
    }
    if (L1) {
        atomicAdd(&g_sum[f + 0], s.x);  atomicAdd(&g_sum[f + 1], s.y);
        atomicAdd(&g_sum[f + 2], s.z);  atomicAdd(&g_sum[f + 3], s.w);
        atomicAdd(&g_sumsq[f + 0], s2.x); atomicAdd(&g_sumsq[f + 1], s2.y);
        atomicAdd(&g_sumsq[f + 2], s2.z); atomicAdd(&g_sumsq[f + 3], s2.w);
    }
}

__global__ void bn_finalize(const float* __restrict__ gamma, const float* __restrict__ beta,
                            float invM) {
    int f = threadIdx.x;
    float mean = g_sum[f] * invM;
    float var = fmaf(-mean, mean, g_sumsq[f] * invM);
    float rstd = rsqrtf(var + 1e-5f);
    float sc = gamma[f] * rstd;
    g_bnsc[f] = sc;
    g_bnsh[f] = fmaf(-mean, sc, beta[f]);
}

extern "C" void kernel_launch(void* const* d_in, const int* in_sizes, int n_in,
                              void* d_out, int out_size) {
    const float* x     = (const float*)d_in[0];
    const void*  eidx  = d_in[1];
    const float* W1    = (const float*)d_in[2];
    const float* b1    = (const float*)d_in[3];
    const float* gamma = (const float*)d_in[4];
    const float* beta  = (const float*)d_in[5];
    const float* W2    = (const float*)d_in[6];
    const float* b2    = (const float*)d_in[7];
    float* out = (float*)d_out;

    const int Kin = 128;
    const int M = in_sizes[0] / Kin;     // 50000
    const int E = in_sizes[1] / 2;       // 800000
    const int NB = (M + SCAN_B - 1) / SCAN_B;

    float *hs, *acc;
    cudaGetSymbolAddress((void**)&hs, g_hs);
    cudaGetSymbolAddress((void**)&acc, g_acc);

    detect_kernel<<<1, 256>>>((const unsigned*)eidx, E);
    init_kernel<<<(M + 255) / 256, 256>>>(M);
    count_kernel<<<(E + 255) / 256, 256>>>(eidx, E);
    scanA_kernel<<<NB, SCAN_B>>>(M);
    scanB_kernel<<<1, 256>>>(NB, M);
    scanC_kernel<<<NB, SCAN_B>>>(M);
    fill_kernel<<<(E + 255) / 256, 256>>>(eidx, E);

    dim3 gemm_grid(HID / 128, (M + 127) / 128);
    // layer 1: hs = (x@W1)*dinv[row]
    sgemm_scaled<128, false><<<gemm_grid, 256>>>(x, W1, hs, M);
    // gather + relu + bias + BN stats -> acc
    gather_kernel<true><<<2960, 256>>>(hs, b1, acc, M);
    bn_finalize<<<1, 256>>>(gamma, beta, 1.0f / (float)M);

    // layer 2: BN folded into A-load; output scaled by dinv -> hs
    sgemm_scaled<256, true><<<gemm_grid, 256>>>(acc, W2, hs, M);
    // gather + bias -> d_out
    gather_kernel<false><<<2960, 256>>>(hs, b2, out, M);
}

// round 4
// speedup vs baseline: 1.6396x; 1.0134x over previous
#include <cuda_runtime.h>

#define MAXN 50000
#define MAXE 800000
#define HID 256
#define SCAN_B 256

// ---- device scratch (no allocs allowed) ----
__device__ float g_hs[(size_t)MAXN * HID];
__device__ float g_acc[(size_t)MAXN * HID];
__device__ float g_dinv[MAXN];
__device__ int   g_cnt[MAXN];
__device__ int   g_off[MAXN + 1];
__device__ int   g_cur[MAXN];
__device__ int   g_csr[MAXE];
__device__ int   g_bsum[(MAXN + SCAN_B - 1) / SCAN_B + 1];
__device__ float g_sum[HID];
__device__ float g_sumsq[HID];
__device__ float g_bnsc[HID];
__device__ float g_bnsh[HID];
__device__ int   g_is64;

// ---- detect edge-index width (int64 vs int32) ----
__global__ void detect_kernel(const unsigned* __restrict__ e, int E) {
    __shared__ int any;
    if (threadIdx.x == 0) any = 0;
    __syncthreads();
    int nchk = 1024; if (nchk > E) nchk = E;
    int loc = 0;
    for (int i = threadIdx.x; i < nchk; i += blockDim.x) {
        if (e[2 * i + 1] != 0u) loc = 1;
    }
    if (loc) atomicOr(&any, 1);
    __syncthreads();
    if (threadIdx.x == 0) g_is64 = (any == 0);
}

__global__ void init_kernel(int M) {
    int i = blockIdx.x * blockDim.x + threadIdx.x;
    if (i < M) g_cnt[i] = 0;
    if (i < HID) { g_sum[i] = 0.0f; g_sumsq[i] = 0.0f; }
}

__global__ void count_kernel(const void* __restrict__ e, int E) {
    int i = blockIdx.x * blockDim.x + threadIdx.x;
    if (i >= E) return;
    int d = g_is64 ? (int)((const long long*)e)[E + i] : ((const int*)e)[E + i];
    atomicAdd(&g_cnt[d], 1);
}

__global__ void scanA_kernel(int M) {
    int i = blockIdx.x * SCAN_B + threadIdx.x;
    int v = (i < M) ? g_cnt[i] : 0;
#pragma unroll
    for (int o = 16; o > 0; o >>= 1) v += __shfl_down_sync(0xffffffffu, v, o);
    __shared__ int ws[8];
    int lane = threadIdx.x & 31, warp = threadIdx.x >> 5;
    if (lane == 0) ws[warp] = v;
    __syncthreads();
    if (warp == 0) {
        int s = (lane < 8) ? ws[lane] : 0;
#pragma unroll
        for (int o = 4; o > 0; o >>= 1) s += __shfl_down_sync(0xffffffffu, s, o);
        if (lane == 0) g_bsum[blockIdx.x] = s;
    }
}

__global__ void scanB_kernel(int NB, int M) {
    int i = threadIdx.x;
    int v = (i < NB) ? g_bsum[i] : 0;
    int x = v;
#pragma unroll
    for (int o = 1; o < 32; o <<= 1) {
        int t = __shfl_up_sync(0xffffffffu, x, o);
        if ((threadIdx.x & 31) >= o) x += t;
    }
    __shared__ int ws[8];
    int lane = threadIdx.x & 31, warp = threadIdx.x >> 5;
    if (lane == 31) ws[warp] = x;
    __syncthreads();
    if (warp == 0 && lane < 8) {
        int s = ws[lane];
#pragma unroll
        for (int o = 1; o < 8; o <<= 1) {
            int t = __shfl_up_sync(0xffu, s, o);
            if (lane >= o) s += t;
        }
        ws[lane] = s;
    }
    __syncthreads();
    int incl = x + (warp > 0 ? ws[warp - 1] : 0);
    if (i < NB) g_bsum[i] = incl - v;
    if (i == NB - 1) g_off[M] = incl;
}

__global__ void scanC_kernel(int M) {
    int i = blockIdx.x * SCAN_B + threadIdx.x;
    int v = (i < M) ? g_cnt[i] : 0;
    int x = v;
#pragma unroll
    for (int o = 1; o < 32; o <<= 1) {
        int t = __shfl_up_sync(0xffffffffu, x, o);
        if ((threadIdx.x & 31) >= o) x += t;
    }
    __shared__ int ws[8];
    int lane = threadIdx.x & 31, warp = threadIdx.x >> 5;
    if (lane == 31) ws[warp] = x;
    __syncthreads();
    if (warp == 0 && lane < 8) {
        int s = ws[lane];
#pragma unroll
        for (int o = 1; o < 8; o <<= 1) {
            int t = __shfl_up_sync(0xffu, s, o);
            if (lane >= o) s += t;
        }
        ws[lane] = s;
    }
    __syncthreads();
    if (i < M) {
        int excl = x - v + (warp > 0 ? ws[warp - 1] : 0) + g_bsum[blockIdx.x];
        g_off[i] = excl;
        g_cur[i] = excl;
        g_dinv[i] = rsqrtf((float)(v + 1));
    }
}

__global__ void fill_kernel(const void* __restrict__ e, int E) {
    int i = blockIdx.x * blockDim.x + threadIdx.x;
    if (i >= E) return;
    int s, d;
    if (g_is64) {
        const long long* p = (const long long*)e;
        s = (int)p[i]; d = (int)p[E + i];
    } else {
        const int* p = (const int*)e;
        s = p[i]; d = p[E + i];
    }
    int pos = atomicAdd(&g_cur[d], 1);
    g_csr[pos] = s;
}

// ---- tf32 helpers ----
__device__ __forceinline__ void tf32_split(float x, unsigned& hi, unsigned& lo) {
    unsigned h;
    asm("cvt.rna.tf32.f32 %0, %1;" : "=r"(h) : "f"(x));
    float l = x - __uint_as_float(h);
    unsigned lw;
    asm("cvt.rna.tf32.f32 %0, %1;" : "=r"(lw) : "f"(l));
    hi = h; lo = lw;
}

__device__ __forceinline__ void mma_tf32(float* d, const unsigned* a, const unsigned* b) {
    asm volatile(
        "mma.sync.aligned.m16n8k8.row.col.f32.tf32.tf32.f32 "
        "{%0,%1,%2,%3}, {%4,%5,%6,%7}, {%8,%9}, {%0,%1,%2,%3};\n"
        : "+f"(d[0]), "+f"(d[1]), "+f"(d[2]), "+f"(d[3])
        : "r"(a[0]), "r"(a[1]), "r"(a[2]), "r"(a[3]), "r"(b[0]), "r"(b[1]));
}

// ---- tf32x3 tensor-core GEMM: C[M,256] = A[M,K] @ B[K,256]; epilogue *dinv[row].
//      APPLY_BN folds y = a*bnsc[k] + bnsh[k] into the A-tile global load.
//      Block tile 128x128, 512 threads (16 warps, 32x32 warp tiles), BK=16,
//      double-buffered smem (A padded to 20, B padded to 136: conflict-free frag loads).
template <int K, bool APPLY_BN>
__global__ void __launch_bounds__(512)
sgemm_tf32(const float* __restrict__ A, const float* __restrict__ B,
           float* __restrict__ out0, int M) {
    const int N = HID;
    __shared__ float As[2][128][20];
    __shared__ float Bs[2][16][136];
    const int tid = threadIdx.x;
    const int warpId = tid >> 5;
    const int lane = tid & 31;
    const int group = lane >> 2, tig = lane & 3;
    const int wm = (warpId & 3) * 32;
    const int wn = (warpId >> 2) * 32;
    const int rowBase = blockIdx.y * 128;
    const int colBase = blockIdx.x * 128;

    float acc[2][4][4];
#pragma unroll
    for (int mt = 0; mt < 2; mt++)
#pragma unroll
        for (int nt = 0; nt < 4; nt++)
#pragma unroll
            for (int q = 0; q < 4; q++) acc[mt][nt][q] = 0.0f;

    // global load mapping: one float4 per thread per tile
    const int aRow = tid >> 2;           // 0..127
    const int aQ = (tid & 3) * 4;        // k-col within BK
    const int bRow = tid >> 5;           // 0..15
    const int bCol = lane * 4;           // 0..124

    int aRowG = rowBase + aRow;
    if (aRowG >= M) aRowG = M - 1;
    const float* Aptr = A + (long long)aRowG * K;

    const int NT = K / 16;
    float4 av, bv;

    // preload tile 0
    {
        av = *(const float4*)(Aptr + aQ);
        if (APPLY_BN) {
            const float4 sc = *(const float4*)(g_bnsc + aQ);
            const float4 sh = *(const float4*)(g_bnsh + aQ);
            av.x = fmaf(av.x, sc.x, sh.x); av.y = fmaf(av.y, sc.y, sh.y);
            av.z = fmaf(av.z, sc.z, sh.z); av.w = fmaf(av.w, sc.w, sh.w);
        }
        bv = *(const float4*)(B + (long long)bRow * N + colBase + bCol);
        As[0][aRow][aQ + 0] = av.x; As[0][aRow][aQ + 1] = av.y;
        As[0][aRow][aQ + 2] = av.z; As[0][aRow][aQ + 3] = av.w;
        Bs[0][bRow][bCol + 0] = bv.x; Bs[0][bRow][bCol + 1] = bv.y;
        Bs[0][bRow][bCol + 2] = bv.z; Bs[0][bRow][bCol + 3] = bv.w;
    }
    __syncthreads();

    for (int kt = 0; kt < NT; kt++) {
        const int cur = kt & 1;
        const bool more = (kt + 1 < NT);
        if (more) {
            const int kb = (kt + 1) * 16;
            av = *(const float4*)(Aptr + kb + aQ);
            if (APPLY_BN) {
                const float4 sc = *(const float4*)(g_bnsc + kb + aQ);
                const float4 sh = *(const float4*)(g_bnsh + kb + aQ);
                av.x = fmaf(av.x, sc.x, sh.x); av.y = fmaf(av.y, sc.y, sh.y);
                av.z = fmaf(av.z, sc.z, sh.z); av.w = fmaf(av.w, sc.w, sh.w);
            }
            bv = *(const float4*)(B + (long long)(kb + bRow) * N + colBase + bCol);
        }

#pragma unroll
        for (int ksub = 0; ksub < 2; ksub++) {
            const int k0 = ksub * 8;
            unsigned ah[2][4], al[2][4], bh[4][2], bl[4][2];
#pragma unroll
            for (int mt = 0; mt < 2; mt++) {
                const int r = wm + mt * 16 + group;
                tf32_split(As[cur][r][k0 + tig],         ah[mt][0], al[mt][0]);
                tf32_split(As[cur][r + 8][k0 + tig],     ah[mt][1], al[mt][1]);
                tf32_split(As[cur][r][k0 + tig + 4],     ah[mt][2], al[mt][2]);
                tf32_split(As[cur][r + 8][k0 + tig + 4], ah[mt][3], al[mt][3]);
            }
#pragma unroll
            for (int nt = 0; nt < 4; nt++) {
                const int c = wn + nt * 8 + group;
                tf32_split(Bs[cur][k0 + tig][c],     bh[nt][0], bl[nt][0]);
                tf32_split(Bs[cur][k0 + tig + 4][c], bh[nt][1], bl[nt][1]);
            }
#pragma unroll
            for (int mt = 0; mt < 2; mt++)
#pragma unroll
                for (int nt = 0; nt < 4; nt++) {
                    mma_tf32(acc[mt][nt], ah[mt], bh[nt]);
                    mma_tf32(acc[mt][nt], al[mt], bh[nt]);
                    mma_tf32(acc[mt][nt], ah[mt], bl[nt]);
                }
        }

        if (more) {
            const int nxt = cur ^ 1;
            As[nxt][aRow][aQ + 0] = av.x; As[nxt][aRow][aQ + 1] = av.y;
            As[nxt][aRow][aQ + 2] = av.z; As[nxt][aRow][aQ + 3] = av.w;
            Bs[nxt][bRow][bCol + 0] = bv.x; Bs[nxt][bRow][bCol + 1] = bv.y;
            Bs[nxt][bRow][bCol + 2] = bv.z; Bs[nxt][bRow][bCol + 3] = bv.w;
            __syncthreads();
        }
    }

    // epilogue: scale rows by dinv, float2 stores
#pragma unroll
    for (int mt = 0; mt < 2; mt++) {
        const int r0 = rowBase + wm + mt * 16 + group;
        const int r1 = r0 + 8;
        const float d0 = (r0 < M) ? g_dinv[r0] : 0.0f;
        const float d1 = (r1 < M) ? g_dinv[r1] : 0.0f;
#pragma unroll
        for (int nt = 0; nt < 4; nt++) {
            const int c = colBase + wn + nt * 8 + tig * 2;
            if (r0 < M) {
                float2 v; v.x = acc[mt][nt][0] * d0; v.y = acc[mt][nt][1] * d0;
                *(float2*)(out0 + (size_t)r0 * N + c) = v;
            }
            if (r1 < M) {
                float2 v; v.x = acc[mt][nt][2] * d1; v.y = acc[mt][nt][3] * d1;
                *(float2*)(out0 + (size_t)r1 * N + c) = v;
            }
        }
    }
}

// ---- CSR gather aggregation: one 64-thread group per dst row, float4/thread.
template <bool L1>
__global__ void __launch_bounds__(256)
gather_kernel(const float* __restrict__ srcf, const float* __restrict__ bias,
              float* __restrict__ out, int M) {
    const int grp = threadIdx.x >> 6;
    const int f = (threadIdx.x & 63) * 4;
    const float4 bb = *(const float4*)(bias + f);
    float4 s = make_float4(0, 0, 0, 0), s2 = make_float4(0, 0, 0, 0);

    for (int r = blockIdx.x * 4 + grp; r < M; r += gridDim.x * 4) {
        int beg = g_off[r], end = g_off[r + 1];
        float4 acc = *(const float4*)(srcf + (size_t)r * HID + f);   // self loop
        int e = beg;
        for (; e + 4 <= end; e += 4) {
            int i0 = g_csr[e], i1 = g_csr[e + 1], i2 = g_csr[e + 2], i3 = g_csr[e + 3];
            float4 v0 = *(const float4*)(srcf + (size_t)i0 * HID + f);
            float4 v1 = *(const float4*)(srcf + (size_t)i1 * HID + f);
            float4 v2 = *(const float4*)(srcf + (size_t)i2 * HID + f);
            float4 v3 = *(const float4*)(srcf + (size_t)i3 * HID + f);
            v0.x += v1.x; v0.y += v1.y; v0.z += v1.z; v0.w += v1.w;
            v2.x += v3.x; v2.y += v3.y; v2.z += v3.z; v2.w += v3.w;
            acc.x += v0.x + v2.x; acc.y += v0.y + v2.y;
            acc.z += v0.z + v2.z; acc.w += v0.w + v2.w;
        }
        for (; e < end; e++) {
            int i0 = g_csr[e];
            float4 v0 = *(const float4*)(srcf + (size_t)i0 * HID + f);
            acc.x += v0.x; acc.y += v0.y; acc.z += v0.z; acc.w += v0.w;
        }
        float dv = g_dinv[r];
        float4 o;
        o.x = fmaf(acc.x, dv, bb.x);
        o.y = fmaf(acc.y, dv, bb.y);
        o.z = fmaf(acc.z, dv, bb.z);
        o.w = fmaf(acc.w, dv, bb.w);
        if (L1) {
            o.x = fmaxf(o.x, 0.0f); o.y = fmaxf(o.y, 0.0f);
            o.z = fmaxf(o.z, 0.0f); o.w = fmaxf(o.w, 0.0f);
            s.x += o.x; s.y += o.y; s.z += o.z; s.w += o.w;
            s2.x += o.x * o.x; s2.y += o.y * o.y;
            s2.z += o.z * o.z; s2.w += o.w * o.w;
        }
        *(float4*)(out + (size_t)r * HID + f) = o;
    }
    if (L1) {
        atomicAdd(&g_sum[f + 0], s.x);  atomicAdd(&g_sum[f + 1], s.y);
        atomicAdd(&g_sum[f + 2], s.z);  atomicAdd(&g_sum[f + 3], s.w);
        atomicAdd(&g_sumsq[f + 0], s2.x); atomicAdd(&g_sumsq[f + 1], s2.y);
        atomicAdd(&g_sumsq[f + 2], s2.z); atomicAdd(&g_sumsq[f + 3], s2.w);
    }
}

__global__ void bn_finalize(const float* __restrict__ gamma, const float* __restrict__ beta,
                            float invM) {
    int f = threadIdx.x;
    float mean = g_sum[f] * invM;
    float var = fmaf(-mean, mean, g_sumsq[f] * invM);
    float rstd = rsqrtf(var + 1e-5f);
    float sc = gamma[f] * rstd;
    g_bnsc[f] = sc;
    g_bnsh[f] = fmaf(-mean, sc, beta[f]);
}

extern "C" void kernel_launch(void* const* d_in, const int* in_sizes, int n_in,
                              void* d_out, int out_size) {
    const float* x     = (const float*)d_in[0];
    const void*  eidx  = d_in[1];
    const float* W1    = (const float*)d_in[2];
    const float* b1    = (const float*)d_in[3];
    const float* gamma = (const float*)d_in[4];
    const float* beta  = (const float*)d_in[5];
    const float* W2    = (const float*)d_in[6];
    const float* b2    = (const float*)d_in[7];
    float* out = (float*)d_out;

    const int Kin = 128;
    const int M = in_sizes[0] / Kin;     // 50000
    const int E = in_sizes[1] / 2;       // 800000
    const int NB = (M + SCAN_B - 1) / SCAN_B;

    float *hs, *acc;
    cudaGetSymbolAddress((void**)&hs, g_hs);
    cudaGetSymbolAddress((void**)&acc, g_acc);

    detect_kernel<<<1, 256>>>((const unsigned*)eidx, E);
    init_kernel<<<(M + 255) / 256, 256>>>(M);
    count_kernel<<<(E + 255) / 256, 256>>>(eidx, E);
    scanA_kernel<<<NB, SCAN_B>>>(M);
    scanB_kernel<<<1, 256>>>(NB, M);
    scanC_kernel<<<NB, SCAN_B>>>(M);
    fill_kernel<<<(E + 255) / 256, 256>>>(eidx, E);

    dim3 gemm_grid(HID / 128, (M + 127) / 128);
    // layer 1: hs = (x@W1)*dinv[row]
    sgemm_tf32<128, false><<<gemm_grid, 512>>>(x, W1, hs, M);
    // gather + relu + bias + BN stats -> acc
    gather_kernel<true><<<2960, 256>>>(hs, b1, acc, M);
    bn_finalize<<<1, 256>>>(gamma, beta, 1.0f / (float)M);

    // layer 2: BN folded into A-load; output scaled by dinv -> hs
    sgemm_tf32<256, true><<<gemm_grid, 512>>>(acc, W2, hs, M);
    // gather + bias -> d_out
    gather_kernel<false><<<2960, 256>>>(hs, b2, out, M);
}